// round 5
// baseline (speedup 1.0000x reference)
#include <cuda_runtime.h>
#include <math.h>

#define NMAT 256
#define D 64
#define DD 4096
#define SLD 68            // normal smem row stride (floats)
#define DSTR 132          // duplicated-layout row stride (floats, 16B aligned)
#define LOG_LO 0.45
#define LOG_HI 5.6

typedef unsigned long long ull;

// ---------------- device scratch (static, allocation-free) ----------------
__device__ float g_logX[NMAT * DD];
__device__ float g_Y[NMAT * DD];
__device__ float g_W[NMAT * NMAT];
__device__ float g_gramP[8 * NMAT * NMAT];
__device__ float g_sq[NMAT], g_s[NMAT], g_rowS[NMAT], g_colS[NMAT];

struct CC { float c[3][5]; };   // grouped Chebyshev-PS coefficients (deg 14)

// ---------------- packed f32x2 helpers ------------------------------------
__device__ __forceinline__ ull f2pack(float lo, float hi) {
    ull d; asm("mov.b64 %0, {%1, %2};" : "=l"(d)
               : "r"(__float_as_uint(lo)), "r"(__float_as_uint(hi)));
    return d;
}
__device__ __forceinline__ ull fdup(float x) { return f2pack(x, x); }
__device__ __forceinline__ void f2unpack(ull v, float& lo, float& hi) {
    unsigned a, b; asm("mov.b64 {%0, %1}, %2;" : "=r"(a), "=r"(b) : "l"(v));
    lo = __uint_as_float(a); hi = __uint_as_float(b);
}
__device__ __forceinline__ ull fma2(ull a, ull b, ull c) {
    ull d; asm("fma.rn.f32x2 %0, %1, %2, %3;" : "=l"(d) : "l"(a), "l"(b), "l"(c));
    return d;
}
__device__ __forceinline__ ull add2(ull a, ull b) {
    ull d; asm("add.rn.f32x2 %0, %1, %2;" : "=l"(d) : "l"(a), "l"(b));
    return d;
}
__device__ __forceinline__ ull mul2(ull a, ull b) {
    ull d; asm("mul.rn.f32x2 %0, %1, %2;" : "=l"(d) : "l"(a), "l"(b));
    return d;
}
__device__ __forceinline__ ull neg2(ull a) { return a ^ 0x8000000080000000ULL; }

__device__ __forceinline__ ull dgp(int r, int cb, int jp) {
    return f2pack((cb + 2 * jp == r) ? 1.f : 0.f, (cb + 2 * jp + 1 == r) ? 1.f : 0.f);
}

// ---- packed matmul, A in duplicated layout (stride DSTR), B normal (SLD) --
// C[4ty+i][4tx+2jp..] += sum_k A[k][4ty+i] * B[k][4tx+...]
template <int NK>
__device__ __forceinline__ void mmd(const float* __restrict__ Ad,
                                    const float* __restrict__ B,
                                    ull acc[4][2], int tx, int ty) {
    const float* Ak = Ad + 8 * ty;
    const float* Bk = B + 4 * tx;
#pragma unroll 4
    for (int k = 0; k < NK; k++) {
        ulonglong2 a01 = *(const ulonglong2*)Ak;
        ulonglong2 a23 = *(const ulonglong2*)(Ak + 4);
        ulonglong2 b   = *(const ulonglong2*)Bk;
        acc[0][0] = fma2(a01.x, b.x, acc[0][0]); acc[0][1] = fma2(a01.x, b.y, acc[0][1]);
        acc[1][0] = fma2(a01.y, b.x, acc[1][0]); acc[1][1] = fma2(a01.y, b.y, acc[1][1]);
        acc[2][0] = fma2(a23.x, b.x, acc[2][0]); acc[2][1] = fma2(a23.x, b.y, acc[2][1]);
        acc[3][0] = fma2(a23.y, b.x, acc[3][0]); acc[3][1] = fma2(a23.y, b.y, acc[3][1]);
        Ak += DSTR; Bk += SLD;
    }
}

#define TOFF(buf, i, jp) ((ull*)((buf) + (4 * ty + (i)) * SLD + cb + 2 * (jp)))

// dup build from a normal smem buffer (all 256 threads)
__device__ __forceinline__ void dup_build(float* __restrict__ dst,
                                          const float* __restrict__ src, int t) {
#pragma unroll
    for (int q = 0; q < 16; q++) {
        int l = t + 256 * q;
        int r = l >> 6, c = l & 63;
        float v = src[r * SLD + c];
        *(ull*)&dst[r * DSTR + 2 * c] = f2pack(v, v);
    }
}

// ---------------- matrix log: deg-14 Chebyshev-PS (7 matmuls) -------------
__global__ void __launch_bounds__(256, 2) matlog_kernel(const float* __restrict__ X, CC cc) {
    extern __shared__ float sm[];
    float* bufA = sm;                     // A (normal)
    float* b1   = sm + D * SLD;
    float* b2   = sm + 2 * D * SLD;
    float* bufD = sm + 3 * D * SLD;       // dup buffer (D*DSTR)
    int mat = blockIdx.x, t = threadIdx.x;
    int tx = t & 15, ty = t >> 4, cb = 4 * tx;
    const float inv = (float)(2.0 / (LOG_HI - LOG_LO));
    const float sh  = (float)((LOG_HI + LOG_LO) / (LOG_HI - LOG_LO));

#pragma unroll
    for (int q = 0; q < 16; q++) {
        int l = t + 256 * q;
        int r = l >> 6, c = l & 63;
        float v = X[mat * DD + l] * inv - ((r == c) ? sh : 0.f);
        bufA[r * SLD + c] = v;
        *(ull*)&bufD[r * DSTR + 2 * c] = f2pack(v, v);
    }
    __syncthreads();

    ull RES[4][2], I1[4][2], I2[4][2];
    {
        ull c00 = fdup(cc.c[0][0]), c01 = fdup(cc.c[0][1]);
        ull c10 = fdup(cc.c[1][0]), c11 = fdup(cc.c[1][1]);
        ull c20 = fdup(cc.c[2][0]), c21 = fdup(cc.c[2][1]);
#pragma unroll
        for (int i = 0; i < 4; i++) {
            int r = 4 * ty + i;
#pragma unroll
            for (int jp = 0; jp < 2; jp++) {
                ull a  = *TOFF(bufA, i, jp);
                ull dg = dgp(r, cb, jp);
                RES[i][jp] = fma2(a, c01, mul2(dg, c00));
                I1[i][jp]  = fma2(a, c11, mul2(dg, c10));
                I2[i][jp]  = fma2(a, c21, mul2(dg, c20));
            }
        }
    }
    // T2 = 2*A*A - I -> b1
    {
        ull acc[4][2] = {}; mmd<D>(bufD, bufA, acc, tx, ty);
        ull w0 = fdup(cc.c[0][2]), w1 = fdup(cc.c[1][2]), w2 = fdup(cc.c[2][2]);
#pragma unroll
        for (int i = 0; i < 4; i++) { int r = 4 * ty + i;
#pragma unroll
            for (int jp = 0; jp < 2; jp++) {
                ull v = add2(add2(acc[i][jp], acc[i][jp]), neg2(dgp(r, cb, jp)));
                *TOFF(b1, i, jp) = v;
                RES[i][jp] = fma2(v, w0, RES[i][jp]);
                I1[i][jp]  = fma2(v, w1, I1[i][jp]);
                I2[i][jp]  = fma2(v, w2, I2[i][jp]);
            } }
        __syncthreads();
    }
    // T3 = 2*A*T2 - A -> b2
    {
        ull acc[4][2] = {}; mmd<D>(bufD, b1, acc, tx, ty);
        ull w0 = fdup(cc.c[0][3]), w1 = fdup(cc.c[1][3]), w2 = fdup(cc.c[2][3]);
#pragma unroll
        for (int i = 0; i < 4; i++)
#pragma unroll
            for (int jp = 0; jp < 2; jp++) {
                ull v = add2(add2(acc[i][jp], acc[i][jp]), neg2(*TOFF(bufA, i, jp)));
                *TOFF(b2, i, jp) = v;
                RES[i][jp] = fma2(v, w0, RES[i][jp]);
                I1[i][jp]  = fma2(v, w1, I1[i][jp]);
                I2[i][jp]  = fma2(v, w2, I2[i][jp]);
            }
        __syncthreads();
    }
    // T4 = 2*A*T3 - T2 -> b1 (in place)
    {
        ull acc[4][2] = {}; mmd<D>(bufD, b2, acc, tx, ty);
        ull w0 = fdup(cc.c[0][4]), w1 = fdup(cc.c[1][4]), w2 = fdup(cc.c[2][4]);
#pragma unroll
        for (int i = 0; i < 4; i++)
#pragma unroll
            for (int jp = 0; jp < 2; jp++) {
                ull* p = TOFF(b1, i, jp);
                ull v = add2(add2(acc[i][jp], acc[i][jp]), neg2(*p));
                *p = v;
                RES[i][jp] = fma2(v, w0, RES[i][jp]);
                I1[i][jp]  = fma2(v, w1, I1[i][jp]);
                I2[i][jp]  = fma2(v, w2, I2[i][jp]);
            }
        __syncthreads();
    }
    // T5 = 2*A*T4 - T3 -> b2 (in place)
    {
        ull acc[4][2] = {}; mmd<D>(bufD, b1, acc, tx, ty);
#pragma unroll
        for (int i = 0; i < 4; i++)
#pragma unroll
            for (int jp = 0; jp < 2; jp++) {
                ull* p = TOFF(b2, i, jp);
                *p = add2(add2(acc[i][jp], acc[i][jp]), neg2(*p));
            }
        __syncthreads();
    }
    // build dup(T5); dump I1 -> bufA (A dead)
    dup_build(bufD, b2, t);
#pragma unroll
    for (int i = 0; i < 4; i++)
#pragma unroll
        for (int jp = 0; jp < 2; jp++) *TOFF(bufA, i, jp) = I1[i][jp];
    __syncthreads();
    // RES += T5*I1 ; T10 = 2*T5*T5 - I -> b1
    {
        ull acc[4][2] = {}; mmd<D>(bufD, bufA, acc, tx, ty);
#pragma unroll
        for (int i = 0; i < 4; i++)
#pragma unroll
            for (int jp = 0; jp < 2; jp++) RES[i][jp] = add2(RES[i][jp], acc[i][jp]);
    }
    {
        ull acc[4][2] = {}; mmd<D>(bufD, b2, acc, tx, ty);
#pragma unroll
        for (int i = 0; i < 4; i++) { int r = 4 * ty + i;
#pragma unroll
            for (int jp = 0; jp < 2; jp++)
                *TOFF(b1, i, jp) = add2(add2(acc[i][jp], acc[i][jp]), neg2(dgp(r, cb, jp)));
        }
    }
    __syncthreads();
    // dump dup(I2) -> bufD (T5 dup dead)
#pragma unroll
    for (int i = 0; i < 4; i++) { int rr = 4 * ty + i;
#pragma unroll
        for (int jp = 0; jp < 2; jp++) {
            float v0, v1; f2unpack(I2[i][jp], v0, v1);
            *(ull*)&bufD[rr * DSTR + 2 * (cb + 2 * jp)]     = f2pack(v0, v0);
            *(ull*)&bufD[rr * DSTR + 2 * (cb + 2 * jp) + 2] = f2pack(v1, v1);
        } }
    __syncthreads();
    // RES += I2*T10  (commutes: all are polynomials of A)
    {
        ull acc[4][2] = {}; mmd<D>(bufD, b1, acc, tx, ty);
#pragma unroll
        for (int i = 0; i < 4; i++)
#pragma unroll
            for (int jp = 0; jp < 2; jp++) RES[i][jp] = add2(RES[i][jp], acc[i][jp]);
    }
    // output + per-matrix sum / sumsq
    float ls = 0.f, lq = 0.f;
#pragma unroll
    for (int i = 0; i < 4; i++)
#pragma unroll
        for (int jp = 0; jp < 2; jp++) {
            float v0, v1; f2unpack(RES[i][jp], v0, v1);
            ls += v0 + v1; lq += v0 * v0 + v1 * v1;
            *(ull*)(&g_logX[mat * DD + (4 * ty + i) * 64 + cb + 2 * jp]) = RES[i][jp];
        }
    __syncthreads();
    b2[t] = ls; b2[256 + t] = lq;
    __syncthreads();
    for (int off = 128; off > 0; off >>= 1) {
        if (t < off) { b2[t] += b2[t + off]; b2[256 + t] += b2[256 + t + off]; }
        __syncthreads();
    }
    if (t == 0) { g_s[mat] = b2[0]; g_sq[mat] = b2[256]; }
}

// ---------------- gram partials: gram = L L^T, K split 8 ways -------------
__global__ void gram_kernel() {
    __shared__ __align__(16) float AsD[64][SLD];  // dup'd 32 rows
    __shared__ __align__(16) float Bs[64][34];
    int bi = blockIdx.x, bj = blockIdx.y, bz = blockIdx.z;
    int t = threadIdx.x, tx = t & 15, ty = t >> 4;
    ull acc[2] = {0ULL, 0ULL};
    for (int kc = 0; kc < 512; kc += 64) {
        int kb = bz * 512 + kc;
#pragma unroll
        for (int q = 0; q < 8; q++) {
            int l = t + 256 * q;
            int r = l >> 6, c = l & 63;
            float va = g_logX[(bi * 32 + r) * DD + kb + c];
            *(ull*)&AsD[c][2 * r] = f2pack(va, va);
            Bs[c][r] = g_logX[(bj * 32 + r) * DD + kb + c];
        }
        __syncthreads();
#pragma unroll 8
        for (int kk = 0; kk < 64; kk++) {
            ulonglong2 a = *(const ulonglong2*)&AsD[kk][4 * ty];
            ull bv = *(const ull*)&Bs[kk][2 * tx];
            acc[0] = fma2(a.x, bv, acc[0]);
            acc[1] = fma2(a.y, bv, acc[1]);
        }
        __syncthreads();
    }
#pragma unroll
    for (int a = 0; a < 2; a++)
        *(ull*)&g_gramP[bz * 65536 + (bi * 32 + 2 * ty + a) * 256 + (bj * 32 + 2 * tx)] = acc[a];
}

// -------- fused W + row/col sums (gram is symmetric; only eps term flips) --
__global__ void wrc_kernel(const float* __restrict__ bwp) {
    __shared__ float sr[256], sc[256];
    int k = blockIdx.x, j = threadIdx.x;
    float g = 0.f;
#pragma unroll
    for (int z = 0; z < 8; z++) g += g_gramP[z * 65536 + k * 256 + j];
    const float eps = 1e-7f;
    float base = g_sq[k] + g_sq[j] - 2.f * g + eps * eps * (float)DD;
    float dlt  = 2.f * eps * (g_s[j] - g_s[k]);
    float bw = bwp[0];
    float ib = -0.5f / (bw * bw);
    float w  = expf(ib * (base + dlt));    // W[k][j]
    float w2 = expf(ib * (base - dlt));    // W[j][k]
    g_W[k * 256 + j] = w;
    sr[j] = w; sc[j] = w2;
    __syncthreads();
    for (int off = 128; off > 0; off >>= 1) {
        if (j < off) { sr[j] += sr[j + off]; sc[j] += sc[j + off]; }
        __syncthreads();
    }
    if (j == 0) { g_rowS[k] = sr[0]; g_colS[k] = sc[0]; }
}

// ---------------- Y = logX + M  (fused W^T * L GEMM epilogue) -------------
__global__ void ygemm_kernel() {
    __shared__ __align__(16) float WsD[32][DSTR];
    __shared__ __align__(16) float Ls[32][SLD];
    int bab = blockIdx.x, bk = blockIdx.y;
    int t = threadIdx.x, tx = t & 15, ty = t >> 4;
    int cb = 4 * tx;
    ull acc[4][2] = {};
    for (int jc = 0; jc < 256; jc += 32) {
#pragma unroll
        for (int q = 0; q < 8; q++) {
            int l = t + 256 * q;
            int jj = l >> 6, c = l & 63;
            float w = g_W[(jc + jj) * 256 + bk * 64 + c];
            *(ull*)&WsD[jj][2 * c] = f2pack(w, w);
            Ls[jj][c] = g_logX[(jc + jj) * DD + bab * 64 + c];
        }
        __syncthreads();
        mmd<32>(&WsD[0][0], &Ls[0][0], acc, tx, ty);
        __syncthreads();
    }
#pragma unroll
    for (int i = 0; i < 4; i++) {
        int k = bk * 64 + 4 * ty + i;
        float rs = g_rowS[k], cs = g_colS[k];
        ull al = fdup(1.f - cs / rs), be = fdup(1.f / rs);
#pragma unroll
        for (int jp = 0; jp < 2; jp++) {
            int ab = bab * 64 + cb + 2 * jp;
            ull lx = *(const ull*)&g_logX[k * DD + ab];
            *(ull*)&g_Y[k * DD + ab] = fma2(lx, al, mul2(acc[i][jp], be));
        }
    }
}

// --------- matrix exp: scaling & squaring (theta=1) + Taylor-8 PS ---------
__global__ void __launch_bounds__(256, 2) matexp_kernel(float* __restrict__ out) {
    extern __shared__ float sm[];
    float* bufA = sm;
    float* b1   = sm + D * SLD;
    float* b2   = sm + 2 * D * SLD;
    float* bufD = sm + 3 * D * SLD;
    int mat = blockIdx.x, t = threadIdx.x;
    int tx = t & 15, ty = t >> 4, cb = 4 * tx;
    float lq = 0.f;
#pragma unroll
    for (int q = 0; q < 16; q++) {
        int l = t + 256 * q;
        int r = l >> 6, c = l & 63;
        float v = g_Y[mat * DD + l];
        bufA[r * SLD + c] = v;
        lq += v * v;
    }
    b1[t] = lq;
    __syncthreads();
    for (int off = 128; off > 0; off >>= 1) {
        if (t < off) b1[t] += b1[t + off];
        __syncthreads();
    }
    float fro = sqrtf(b1[0]);
    __syncthreads();
    int s = 0;
    while (fro > 1.0f && s < 12) { fro *= 0.5f; s++; }
    float scale = ldexpf(1.f, -s);
#pragma unroll
    for (int q = 0; q < 16; q++) {
        int l = t + 256 * q;
        int r = l >> 6, c = l & 63;
        float v = bufA[r * SLD + c] * scale;
        bufA[r * SLD + c] = v;
        *(ull*)&bufD[r * DSTR + 2 * c] = f2pack(v, v);
    }
    __syncthreads();

    const float cf[9] = {1.f, 1.f, 0.5f, 1.f / 6.f, 1.f / 24.f, 1.f / 120.f,
                         1.f / 720.f, 1.f / 5040.f, 1.f / 40320.f};
    ull Q0[4][2], Q1[4][2], Q2[4][2];
    {
        ull k0 = fdup(cf[0]), k1 = fdup(cf[1]);
        ull k3 = fdup(cf[3]), k4 = fdup(cf[4]);
        ull k6 = fdup(cf[6]), k7 = fdup(cf[7]);
#pragma unroll
        for (int i = 0; i < 4; i++) { int r = 4 * ty + i;
#pragma unroll
            for (int jp = 0; jp < 2; jp++) {
                ull a  = *TOFF(bufA, i, jp);
                ull dg = dgp(r, cb, jp);
                Q0[i][jp] = fma2(a, k1, mul2(dg, k0));
                Q1[i][jp] = fma2(a, k4, mul2(dg, k3));
                Q2[i][jp] = fma2(a, k7, mul2(dg, k6));
            } }
    }
    // A2 -> b1
    {
        ull acc[4][2] = {}; mmd<D>(bufD, bufA, acc, tx, ty);
        ull k2 = fdup(cf[2]), k5 = fdup(cf[5]), k8 = fdup(cf[8]);
#pragma unroll
        for (int i = 0; i < 4; i++)
#pragma unroll
            for (int jp = 0; jp < 2; jp++) {
                ull v = acc[i][jp];
                *TOFF(b1, i, jp) = v;
                Q0[i][jp] = fma2(v, k2, Q0[i][jp]);
                Q1[i][jp] = fma2(v, k5, Q1[i][jp]);
                Q2[i][jp] = fma2(v, k8, Q2[i][jp]);
            }
        __syncthreads();
    }
    // A3 -> b2
    {
        ull acc[4][2] = {}; mmd<D>(bufD, b1, acc, tx, ty);
#pragma unroll
        for (int i = 0; i < 4; i++)
#pragma unroll
            for (int jp = 0; jp < 2; jp++) *TOFF(b2, i, jp) = acc[i][jp];
        __syncthreads();
    }
    // build dup(A3); dump Q2 -> bufA (A dead)
    dup_build(bufD, b2, t);
#pragma unroll
    for (int i = 0; i < 4; i++)
#pragma unroll
        for (int jp = 0; jp < 2; jp++) *TOFF(bufA, i, jp) = Q2[i][jp];
    __syncthreads();
    // U1 = A3*Q2 + Q1  (regs), then overwrite bufA with U1
    {
        ull acc[4][2] = {}; mmd<D>(bufD, bufA, acc, tx, ty);
        __syncthreads();
#pragma unroll
        for (int i = 0; i < 4; i++)
#pragma unroll
            for (int jp = 0; jp < 2; jp++)
                *TOFF(bufA, i, jp) = add2(acc[i][jp], Q1[i][jp]);
        __syncthreads();
    }
    // R = A3*U1 + Q0 -> b1
    {
        ull acc[4][2] = {}; mmd<D>(bufD, bufA, acc, tx, ty);
#pragma unroll
        for (int i = 0; i < 4; i++)
#pragma unroll
            for (int jp = 0; jp < 2; jp++)
                *TOFF(b1, i, jp) = add2(acc[i][jp], Q0[i][jp]);
        __syncthreads();
    }
    // s squarings
    float* cur = b1; float* nxt = b2;
    for (int it = 0; it < s; it++) {
        dup_build(bufD, cur, t);
        __syncthreads();
        ull acc[4][2] = {}; mmd<D>(bufD, cur, acc, tx, ty);
#pragma unroll
        for (int i = 0; i < 4; i++)
#pragma unroll
            for (int jp = 0; jp < 2; jp++) *TOFF(nxt, i, jp) = acc[i][jp];
        __syncthreads();
        float* tmp = cur; cur = nxt; nxt = tmp;
    }
#pragma unroll
    for (int i = 0; i < 4; i++)
#pragma unroll
        for (int jp = 0; jp < 2; jp++)
            *(ull*)&out[mat * DD + (4 * ty + i) * 64 + cb + 2 * jp] = *TOFF(cur, i, jp);
}

// ---------------- launch ---------------------------------------------------
extern "C" void kernel_launch(void* const* d_in, const int* in_sizes, int n_in,
                              void* d_out, int out_size) {
    const float* X  = (const float*)d_in[0];
    const float* bw = (const float*)d_in[1];
    for (int i = 0; i < n_in; i++) {
        if (in_sizes[i] == NMAT * DD) X = (const float*)d_in[i];
        else if (in_sizes[i] == 1)    bw = (const float*)d_in[i];
    }
    // host-side deg-14 Chebyshev-PS coefficients (double precision)
    CC cc;
    {
        double mid = 0.5 * (LOG_HI + LOG_LO), half = 0.5 * (LOG_HI - LOG_LO);
        double gam = half / mid;
        double tt = (sqrt(1.0 - gam * gam) - 1.0) / gam;
        double gq[3][5];
        gq[0][0] = log(mid) - log(1.0 + tt * tt);
        double tp = tt;
        for (int k = 1; k < 15; k++) { gq[k / 5][k % 5] = -2.0 * tp / (double)k; tp *= tt; }
        for (int q = 2; q >= 1; q--)
            for (int r = 1; r < 5; r++) gq[q - 1][5 - r] -= gq[q][r];
        for (int r = 0; r < 5; r++) cc.c[0][r] = (float)gq[0][r];
        for (int q = 1; q < 3; q++) {
            cc.c[q][0] = (float)gq[q][0];
            for (int r = 1; r < 5; r++) cc.c[q][r] = (float)(2.0 * gq[q][r]);
        }
    }
    int smem = (3 * D * SLD + D * DSTR) * (int)sizeof(float);
    cudaFuncSetAttribute(matlog_kernel, cudaFuncAttributeMaxDynamicSharedMemorySize, smem);
    cudaFuncSetAttribute(matexp_kernel, cudaFuncAttributeMaxDynamicSharedMemorySize, smem);

    matlog_kernel<<<NMAT, 256, smem>>>(X, cc);
    gram_kernel<<<dim3(8, 8, 8), 256>>>();
    wrc_kernel<<<NMAT, 256>>>(bw);
    ygemm_kernel<<<dim3(64, 4), 256>>>();
    matexp_kernel<<<NMAT, 256, smem>>>((float*)d_out);
}